// round 4
// baseline (speedup 1.0000x reference)
#include <cuda_runtime.h>

// Shapes (fixed by the problem)
#define NB   4096          // batch B
#define NP   12            // P = PATCH_NUM - MASK_NUM
#define DIN  640
#define DD   128
#define MP   (NP * NB)     // 49152
#define INV_T    0.25f     // 1/T, T=4
#define KL_SCALE (16.0f / 128.0f)   // T^2 / D

// Scratch (device globals: allocation-free rule)
__device__ float d_hg[NB * DD];
__device__ float d_hp[MP * DD];
__device__ float d_g[NB * DD];
__device__ float d_p[MP * DD];
__device__ float d_pbar[NB * DD];
__device__ float d_part_dil[NB / 8];    // 512
__device__ float d_part_dcl[MP / 8];    // 6144

// ---------------------------------------------------------------------------
// SGEMM: out[m, n] = epilogue( sum_k A[m,k] * W[n,k] + bias[n] )
// N = 128 fixed (full width per CTA), BM = 128, BK = 16, 256 threads,
// 8x8 micro-tile per thread, register prefetch of next K-tile.
// RELU=true  : epilogue = relu, store
// RELU=false : epilogue = +bias then L2-normalize each row, store
// ---------------------------------------------------------------------------
template <bool RELU>
__global__ __launch_bounds__(256)
void gemm128_kernel(const float* __restrict__ A, const float* __restrict__ W,
                    const float* __restrict__ bias, float* __restrict__ out,
                    int K)
{
    __shared__ float As[16][128];   // [k][m]
    __shared__ float Ws[16][128];   // [k][n]

    const int tid  = threadIdx.x;
    const int tx   = tid & 15;      // col group (n)
    const int ty   = tid >> 4;      // row group (m)
    const int m0   = blockIdx.x * 128;
    const int lrow = tid >> 2;      // 0..63
    const int kq   = tid & 3;       // 0..3  (which float4 along K)

    const float* Ap0 = A + (m0 + lrow) * K + kq * 4;
    const float* Ap1 = A + (m0 + lrow + 64) * K + kq * 4;
    const float* Wp0 = W + lrow * K + kq * 4;
    const float* Wp1 = W + (lrow + 64) * K + kq * 4;

    float acc[8][8];
#pragma unroll
    for (int i = 0; i < 8; i++)
#pragma unroll
        for (int j = 0; j < 8; j++) acc[i][j] = 0.0f;

    float4 pa0 = *(const float4*)(Ap0);
    float4 pa1 = *(const float4*)(Ap1);
    float4 pw0 = *(const float4*)(Wp0);
    float4 pw1 = *(const float4*)(Wp1);

    for (int kt = 0; kt < K; kt += 16) {
        __syncthreads();
        As[kq * 4 + 0][lrow]      = pa0.x;
        As[kq * 4 + 1][lrow]      = pa0.y;
        As[kq * 4 + 2][lrow]      = pa0.z;
        As[kq * 4 + 3][lrow]      = pa0.w;
        As[kq * 4 + 0][lrow + 64] = pa1.x;
        As[kq * 4 + 1][lrow + 64] = pa1.y;
        As[kq * 4 + 2][lrow + 64] = pa1.z;
        As[kq * 4 + 3][lrow + 64] = pa1.w;
        Ws[kq * 4 + 0][lrow]      = pw0.x;
        Ws[kq * 4 + 1][lrow]      = pw0.y;
        Ws[kq * 4 + 2][lrow]      = pw0.z;
        Ws[kq * 4 + 3][lrow]      = pw0.w;
        Ws[kq * 4 + 0][lrow + 64] = pw1.x;
        Ws[kq * 4 + 1][lrow + 64] = pw1.y;
        Ws[kq * 4 + 2][lrow + 64] = pw1.z;
        Ws[kq * 4 + 3][lrow + 64] = pw1.w;
        __syncthreads();

        if (kt + 16 < K) {
            pa0 = *(const float4*)(Ap0 + kt + 16);
            pa1 = *(const float4*)(Ap1 + kt + 16);
            pw0 = *(const float4*)(Wp0 + kt + 16);
            pw1 = *(const float4*)(Wp1 + kt + 16);
        }

#pragma unroll
        for (int k = 0; k < 16; k++) {
            float ar[8], br[8];
            float4 a0 = *(const float4*)(&As[k][ty * 8]);
            float4 a1 = *(const float4*)(&As[k][ty * 8 + 4]);
            float4 b0 = *(const float4*)(&Ws[k][tx * 8]);
            float4 b1 = *(const float4*)(&Ws[k][tx * 8 + 4]);
            ar[0] = a0.x; ar[1] = a0.y; ar[2] = a0.z; ar[3] = a0.w;
            ar[4] = a1.x; ar[5] = a1.y; ar[6] = a1.z; ar[7] = a1.w;
            br[0] = b0.x; br[1] = b0.y; br[2] = b0.z; br[3] = b0.w;
            br[4] = b1.x; br[5] = b1.y; br[6] = b1.z; br[7] = b1.w;
#pragma unroll
            for (int i = 0; i < 8; i++)
#pragma unroll
                for (int j = 0; j < 8; j++)
                    acc[i][j] = fmaf(ar[i], br[j], acc[i][j]);
        }
    }

    float bv[8];
#pragma unroll
    for (int j = 0; j < 8; j++) bv[j] = bias[tx * 8 + j];

    if (RELU) {
#pragma unroll
        for (int i = 0; i < 8; i++) {
            const int row = m0 + ty * 8 + i;
            float4 v0, v1;
            v0.x = fmaxf(acc[i][0] + bv[0], 0.0f);
            v0.y = fmaxf(acc[i][1] + bv[1], 0.0f);
            v0.z = fmaxf(acc[i][2] + bv[2], 0.0f);
            v0.w = fmaxf(acc[i][3] + bv[3], 0.0f);
            v1.x = fmaxf(acc[i][4] + bv[4], 0.0f);
            v1.y = fmaxf(acc[i][5] + bv[5], 0.0f);
            v1.z = fmaxf(acc[i][6] + bv[6], 0.0f);
            v1.w = fmaxf(acc[i][7] + bv[7], 0.0f);
            *(float4*)(out + row * DD + tx * 8)     = v0;
            *(float4*)(out + row * DD + tx * 8 + 4) = v1;
        }
    } else {
        // y = acc + bias, then L2-normalize each row (row fully inside CTA,
        // split across the 16 tx-threads of a half-warp).
#pragma unroll
        for (int i = 0; i < 8; i++)
#pragma unroll
            for (int j = 0; j < 8; j++) acc[i][j] += bv[j];

        float ss[8];
#pragma unroll
        for (int i = 0; i < 8; i++) {
            float s = 0.0f;
#pragma unroll
            for (int j = 0; j < 8; j++) s = fmaf(acc[i][j], acc[i][j], s);
            ss[i] = s;
        }
        // reduce across the 16 lanes sharing ty (xor < 16 stays in half-warp)
#pragma unroll
        for (int o = 1; o < 16; o <<= 1) {
#pragma unroll
            for (int i = 0; i < 8; i++)
                ss[i] += __shfl_xor_sync(0xffffffffu, ss[i], o);
        }
#pragma unroll
        for (int i = 0; i < 8; i++) {
            const int row = m0 + ty * 8 + i;
            const float r = rsqrtf(ss[i]);
            float4 v0, v1;
            v0.x = acc[i][0] * r; v0.y = acc[i][1] * r;
            v0.z = acc[i][2] * r; v0.w = acc[i][3] * r;
            v1.x = acc[i][4] * r; v1.y = acc[i][5] * r;
            v1.z = acc[i][6] * r; v1.w = acc[i][7] * r;
            *(float4*)(out + row * DD + tx * 8)     = v0;
            *(float4*)(out + row * DD + tx * 8 + 4) = v1;
        }
    }
}

// ---------------------------------------------------------------------------
// p_bar[b, d] = mean over l of p[l*B + b, d]
// ---------------------------------------------------------------------------
__global__ void pbar_kernel()
{
    const int idx = blockIdx.x * blockDim.x + threadIdx.x;  // [0, NB*DD)
    float s = 0.0f;
#pragma unroll
    for (int l = 0; l < NP; l++) s += d_p[l * (NB * DD) + idx];
    d_pbar[idx] = s * (1.0f / 12.0f);
}

// ---------------------------------------------------------------------------
// Symmetric KL over one D=128 row handled by one warp (4 elems / lane).
// Input: logits z1, z2 (already divided by T).
// Returns sum_d (p1 - p2) * (l1 - l2)  == kl(s=2,t=1)+kl(s=1,t=2) un-scaled.
// ---------------------------------------------------------------------------
__device__ __forceinline__ float warp_sum(float v)
{
#pragma unroll
    for (int o = 16; o > 0; o >>= 1) v += __shfl_xor_sync(0xffffffffu, v, o);
    return v;
}
__device__ __forceinline__ float warp_max(float v)
{
#pragma unroll
    for (int o = 16; o > 0; o >>= 1)
        v = fmaxf(v, __shfl_xor_sync(0xffffffffu, v, o));
    return v;
}

__device__ __forceinline__ float sym_kl(const float z1[4], const float z2[4])
{
    float m1 = fmaxf(fmaxf(z1[0], z1[1]), fmaxf(z1[2], z1[3]));
    float m2 = fmaxf(fmaxf(z2[0], z2[1]), fmaxf(z2[2], z2[3]));
    m1 = warp_max(m1);
    m2 = warp_max(m2);
    float e1[4], e2[4], s1 = 0.0f, s2 = 0.0f;
#pragma unroll
    for (int i = 0; i < 4; i++) {
        e1[i] = __expf(z1[i] - m1); s1 += e1[i];
        e2[i] = __expf(z2[i] - m2); s2 += e2[i];
    }
    s1 = warp_sum(s1);
    s2 = warp_sum(s2);
    const float inv1 = 1.0f / s1, inv2 = 1.0f / s2;
    const float c1 = m1 + __logf(s1), c2 = m2 + __logf(s2);
    float c = 0.0f;
#pragma unroll
    for (int i = 0; i < 4; i++) {
        const float l1 = z1[i] - c1;
        const float l2 = z2[i] - c2;
        c += (e1[i] * inv1 - e2[i] * inv2) * (l1 - l2);
    }
    return warp_sum(c);
}

// ---------------------------------------------------------------------------
// dil: per row b, symmetric KL between g[b] and p_bar[b]. 1 warp / row.
// ---------------------------------------------------------------------------
__global__ __launch_bounds__(256) void dil_kernel()
{
    const int b    = (blockIdx.x * blockDim.x + threadIdx.x) >> 5;
    const int lane = threadIdx.x & 31;
    const float* gr = d_g    + b * DD;
    const float* pr = d_pbar + b * DD;
    float z1[4], z2[4];
#pragma unroll
    for (int i = 0; i < 4; i++) {
        z1[i] = gr[lane + 32 * i] * INV_T;
        z2[i] = pr[lane + 32 * i] * INV_T;
    }
    const float c = sym_kl(z1, z2) * KL_SCALE;

    __shared__ float sm[8];
    if (lane == 0) sm[threadIdx.x >> 5] = c;
    __syncthreads();
    if (threadIdx.x == 0) {
        float s = 0.0f;
#pragma unroll
        for (int w = 0; w < 8; w++) s += sm[w];
        d_part_dil[blockIdx.x] = s;
    }
}

// ---------------------------------------------------------------------------
// dcl: per (l, b) row r = l*B + b, symmetric KL between (g-p)^2 and
// (pbar-p)^2 logits. 1 warp / row.
// ---------------------------------------------------------------------------
__global__ __launch_bounds__(256) void dcl_kernel()
{
    const int r    = (blockIdx.x * blockDim.x + threadIdx.x) >> 5;  // 0..MP-1
    const int lane = threadIdx.x & 31;
    const int b    = r & (NB - 1);
    const float* pp = d_p    + r * DD;
    const float* gr = d_g    + b * DD;
    const float* pb = d_pbar + b * DD;
    float z1[4], z2[4];
#pragma unroll
    for (int i = 0; i < 4; i++) {
        const int d = lane + 32 * i;
        const float pv = pp[d];
        const float t1 = gr[d] - pv;
        const float t2 = pb[d] - pv;
        z1[i] = t1 * t1 * INV_T;
        z2[i] = t2 * t2 * INV_T;
    }
    const float c = sym_kl(z1, z2) * KL_SCALE;

    __shared__ float sm[8];
    if (lane == 0) sm[threadIdx.x >> 5] = c;
    __syncthreads();
    if (threadIdx.x == 0) {
        float s = 0.0f;
#pragma unroll
        for (int w = 0; w < 8; w++) s += sm[w];
        d_part_dcl[blockIdx.x] = s;
    }
}

// ---------------------------------------------------------------------------
// Deterministic final reduction: fixed strided order + fixed tree.
// ---------------------------------------------------------------------------
__global__ __launch_bounds__(256) void finalize_kernel(float* out)
{
    __shared__ float sm[256];
    const int tid = threadIdx.x;

    float s = 0.0f;
    for (int i = tid; i < NB / 8; i += 256) s += d_part_dil[i];
    sm[tid] = s;
    __syncthreads();
    for (int o = 128; o > 0; o >>= 1) {
        if (tid < o) sm[tid] += sm[tid + o];
        __syncthreads();
    }
    if (tid == 0) out[0] = sm[0];
    __syncthreads();

    float s2 = 0.0f;
    for (int i = tid; i < MP / 8; i += 256) s2 += d_part_dcl[i];
    sm[tid] = s2;
    __syncthreads();
    for (int o = 128; o > 0; o >>= 1) {
        if (tid < o) sm[tid] += sm[tid + o];
        __syncthreads();
    }
    if (tid == 0) out[1] = sm[0] * (1.0f / 12.0f);
}

// ---------------------------------------------------------------------------
// Launch
// Inputs (metadata order): ebg, ebp, labelsg, glo_w1, glo_b1, glo_w2, glo_b2,
//                          pat_w1, pat_b1, pat_w2, pat_b2
// ---------------------------------------------------------------------------
extern "C" void kernel_launch(void* const* d_in, const int* in_sizes, int n_in,
                              void* d_out, int out_size)
{
    const float* ebg    = (const float*)d_in[0];
    const float* ebp    = (const float*)d_in[1];
    const float* glo_w1 = (const float*)d_in[3];
    const float* glo_b1 = (const float*)d_in[4];
    const float* glo_w2 = (const float*)d_in[5];
    const float* glo_b2 = (const float*)d_in[6];
    const float* pat_w1 = (const float*)d_in[7];
    const float* pat_b1 = (const float*)d_in[8];
    const float* pat_w2 = (const float*)d_in[9];
    const float* pat_b2 = (const float*)d_in[10];
    float* out = (float*)d_out;

    float *hg, *hp, *g, *p;
    cudaGetSymbolAddress((void**)&hg, d_hg);
    cudaGetSymbolAddress((void**)&hp, d_hp);
    cudaGetSymbolAddress((void**)&g,  d_g);
    cudaGetSymbolAddress((void**)&p,  d_p);

    // Layer 1 (K=640) + ReLU
    gemm128_kernel<true><<<NB / 128, 256>>>(ebg, glo_w1, glo_b1, hg, DIN);
    gemm128_kernel<true><<<MP / 128, 256>>>(ebp, pat_w1, pat_b1, hp, DIN);
    // Layer 2 (K=128) + bias + L2 normalize
    gemm128_kernel<false><<<NB / 128, 256>>>(hg, glo_w2, glo_b2, g, DD);
    gemm128_kernel<false><<<MP / 128, 256>>>(hp, pat_w2, pat_b2, p, DD);
    // p_bar
    pbar_kernel<<<(NB * DD) / 256, 256>>>();
    // losses
    dil_kernel<<<NB / 8, 256>>>();
    dcl_kernel<<<MP / 8, 256>>>();
    finalize_kernel<<<1, 256>>>(out);
}